// round 14
// baseline (speedup 1.0000x reference)
#include <cuda_runtime.h>
#include <cstdint>

#define BATCH 4
#define SEQ   2048
#define DIM   768
#define NH    12
#define HD    64
#define BH    (BATCH*NH)          // 48
#define MROWS (BATCH*SEQ)         // 8192
#define SCALE 0.125f
#define LOG2E 1.4426950408889634f

// Scratch (allocation-free rule: __device__ globals)
__device__ float g_Q[BH*SEQ*HD];         // natural, fp32
__device__ float g_K[BH*SEQ*HD];         // natural, tf32
__device__ float g_V[BH*SEQ*HD];         // natural, tf32
__device__ float g_AO[BATCH*SEQ*DIM];    // natural, tf32
__device__ float g_Xr[MROWS*DIM];        // k-permuted, tf32 (GEMM1 A)
__device__ float g_Wqkvr[3*DIM*DIM];     // k-permuted, tf32 (GEMM1 B)
__device__ float g_Wprojr[DIM*DIM];      // natural, tf32   (GEMM2 B)

__device__ __forceinline__ uint32_t smem_u32(const void* p) {
    uint32_t a;
    asm("{ .reg .u64 t; cvta.to.shared.u64 t, %1; cvt.u32.u64 %0, t; }"
        : "=r"(a) : "l"(p));
    return a;
}

__device__ __forceinline__ uint32_t f2tf32(float x) {
    uint32_t r;
    asm("cvt.rna.tf32.f32 %0, %1;" : "=r"(r) : "f"(x));
    return r;
}
__device__ __forceinline__ float rnaf(float x) {
    return __uint_as_float(f2tf32(x));
}

__device__ __forceinline__ float ex2(float x) {
    float r;
    asm("ex2.approx.ftz.f32 %0, %1;" : "=f"(r) : "f"(x));
    return r;
}

__device__ __forceinline__ void cpa16(uint32_t dst, const void* src) {
    asm volatile("cp.async.cg.shared.global [%0], [%1], 16;"
                 :: "r"(dst), "l"(src));
}
#define CP_COMMIT() asm volatile("cp.async.commit_group;" ::: "memory")
#define CP_WAIT1()  asm volatile("cp.async.wait_group 1;" ::: "memory")
#define CP_WAIT0()  asm volatile("cp.async.wait_group 0;" ::: "memory")

__device__ __forceinline__ void mma_tf32(float c[4], uint32_t a0, uint32_t a1,
                                         uint32_t a2, uint32_t a3,
                                         uint32_t b0, uint32_t b1) {
    asm volatile(
        "mma.sync.aligned.m16n8k8.row.col.f32.tf32.tf32.f32 "
        "{%0,%1,%2,%3}, {%4,%5,%6,%7}, {%8,%9}, {%0,%1,%2,%3};"
        : "+f"(c[0]), "+f"(c[1]), "+f"(c[2]), "+f"(c[3])
        : "r"(a0), "r"(a1), "r"(a2), "r"(a3), "r"(b0), "r"(b1));
}

// ---------------------------------------------------------------------------
// Prep A: tf32-round + k-permute within 8-groups (0,4,1,5,2,6,3,7).
// which: 0 = x -> g_Xr, 1 = w_qkv -> g_Wqkvr
// ---------------------------------------------------------------------------
__global__ __launch_bounds__(256) void round_perm(const float* __restrict__ s,
                                                  int n8, int which)
{
    float* d = (which == 0) ? g_Xr : g_Wqkvr;
    int i = blockIdx.x * 256 + threadIdx.x;
    if (i < n8) {
        float4 a = ((const float4*)s)[2*i];
        float4 b = ((const float4*)s)[2*i+1];
        float4 o0, o1;
        o0.x = rnaf(a.x); o0.y = rnaf(b.x); o0.z = rnaf(a.y); o0.w = rnaf(b.y);
        o1.x = rnaf(a.z); o1.y = rnaf(b.z); o1.z = rnaf(a.w); o1.w = rnaf(b.w);
        ((float4*)d)[2*i]   = o0;
        ((float4*)d)[2*i+1] = o1;
    }
}

// Prep B: plain tf32 rounding (w_proj -> g_Wprojr, natural layout)
__global__ __launch_bounds__(256) void round_plain(const float* __restrict__ s,
                                                   int n4)
{
    int i = blockIdx.x * 256 + threadIdx.x;
    if (i < n4) {
        float4 v = ((const float4*)s)[i];
        v.x = rnaf(v.x); v.y = rnaf(v.y); v.z = rnaf(v.z); v.w = rnaf(v.w);
        ((float4*)g_Wprojr)[i] = v;
    }
}

// ---------------------------------------------------------------------------
// GEMM1 (R13-validated, 174us): qkv = Xr x Wqkvr. cp.async 2-stage ring,
// SSTR=40, k-permuted LDS.64 fragments. Epilogue: Q raw, K/V tf32-rounded,
// all NATURAL layouts (R8-compatible).
// ---------------------------------------------------------------------------
#define KT     32
#define SSTR1  40
#define CH1    (128 * SSTR1)            // 5120
#define GB1    (2 * CH1)                // 10240
#define GSM1   (2 * GB1 * 4)            // 81920

__global__ __launch_bounds__(256) void gemm_qkv()
{
    extern __shared__ float smf[];
    uint32_t sbase = smem_u32(smf);

    const float* A = g_Xr;
    const float* W = g_Wqkvr;
    int tid  = threadIdx.x;
    int w    = tid >> 5, lane = tid & 31;
    int gr   = lane >> 2, qc = lane & 3;
    int wm   = (w & 1) * 64;
    int wn   = (w >> 1) * 32;
    int bm   = blockIdx.x * 128;
    int bn   = blockIdx.y * 128;

    const float* ag[4]; const float* wg[4]; uint32_t soff[4];
    #pragma unroll
    for (int i = 0; i < 4; ++i) {
        int e   = tid + i * 256;
        int row = e >> 3;
        int ks4 = (e & 7) * 4;
        ag[i]   = A + (size_t)(bm + row) * DIM + ks4;
        wg[i]   = W + (size_t)(bn + row) * DIM + ks4;
        soff[i] = (uint32_t)(row * SSTR1 + ks4) * 4u;
    }

    float acc[4][4][4];
    #pragma unroll
    for (int mt = 0; mt < 4; ++mt)
        #pragma unroll
        for (int nt = 0; nt < 4; ++nt)
            #pragma unroll
            for (int i = 0; i < 4; ++i) acc[mt][nt][i] = 0.f;

    const int NC = DIM / KT;

    #pragma unroll
    for (int i = 0; i < 4; ++i) {
        cpa16(sbase + soff[i], ag[i]);
        cpa16(sbase + CH1 * 4 + soff[i], wg[i]);
    }
    CP_COMMIT();

    int buf = 0;
    for (int c = 0; c < NC; ++c) {
        CP_WAIT0();
        __syncthreads();

        if (c + 1 < NC) {
            uint32_t nbb = sbase + (uint32_t)(buf ^ 1) * GB1 * 4u;
            #pragma unroll
            for (int i = 0; i < 4; ++i) {
                cpa16(nbb + soff[i], ag[i] + (c + 1) * KT);
                cpa16(nbb + CH1 * 4 + soff[i], wg[i] + (c + 1) * KT);
            }
            CP_COMMIT();
        }

        const uint32_t* As = (const uint32_t*)(smf + buf * GB1);
        const uint32_t* Bs = As + CH1;

        #pragma unroll
        for (int ks = 0; ks < KT / 8; ++ks) {
            int k0 = ks * 8;
            uint32_t af[4][4], bf[4][2];
            #pragma unroll
            for (int mt = 0; mt < 4; ++mt) {
                uint2 v0 = *(const uint2*)
                    (As + (wm + mt * 16 + gr) * SSTR1 + k0 + 2 * qc);
                uint2 v1 = *(const uint2*)
                    (As + (wm + mt * 16 + 8 + gr) * SSTR1 + k0 + 2 * qc);
                af[mt][0] = v0.x; af[mt][2] = v0.y;
                af[mt][1] = v1.x; af[mt][3] = v1.y;
            }
            #pragma unroll
            for (int nt = 0; nt < 4; ++nt) {
                uint2 v = *(const uint2*)
                    (Bs + (wn + nt * 8 + gr) * SSTR1 + k0 + 2 * qc);
                bf[nt][0] = v.x; bf[nt][1] = v.y;
            }
            #pragma unroll
            for (int mt = 0; mt < 4; ++mt)
                #pragma unroll
                for (int nt = 0; nt < 4; ++nt)
                    mma_tf32(acc[mt][nt], af[mt][0], af[mt][1], af[mt][2],
                             af[mt][3], bf[nt][0], bf[nt][1]);
        }
        buf ^= 1;
    }

    int scol = bn + wn;
    int s   = scol / DIM;
    int rem = scol % DIM;
    int h   = rem / HD;
    int d0  = rem % HD;
    float* dst = (s == 0) ? g_Q : (s == 1) ? g_K : g_V;
    bool rnd = (s != 0);
    #pragma unroll
    for (int mt = 0; mt < 4; ++mt) {
        int r0 = bm + wm + mt * 16 + gr;
        int b  = r0 >> 11, n = r0 & (SEQ - 1);
        float* base = dst + ((size_t)(b * NH + h) * SEQ + n) * HD;
        #pragma unroll
        for (int nt = 0; nt < 4; ++nt) {
            int d = d0 + nt * 8 + 2 * qc;
            float v0 = acc[mt][nt][0], v1 = acc[mt][nt][1];
            float v2 = acc[mt][nt][2], v3 = acc[mt][nt][3];
            if (rnd) { v0 = rnaf(v0); v1 = rnaf(v1);
                       v2 = rnaf(v2); v3 = rnaf(v3); }
            *(float2*)(base + d) = make_float2(v0, v1);
            *(float2*)(base + 8 * HD + d) = make_float2(v2, v3);
        }
    }
}

// ---------------------------------------------------------------------------
// GEMM2 (R8-validated, ~62us): out = AO x Wprojr + bias. 3-stage cp.async
// ring, SSTR=36, scalar fragment loads, natural layouts.
// ---------------------------------------------------------------------------
#define SSTR2  36
#define CH2    (128 * SSTR2)
#define GB2    (2 * CH2)
#define GSM2   (3 * GB2 * 4)            // 110592

__global__ __launch_bounds__(256) void gemm_proj(
    const float* __restrict__ bias, float* __restrict__ out)
{
    extern __shared__ float smf[];
    uint32_t sbase = smem_u32(smf);

    const float* A = g_AO;
    const float* W = g_Wprojr;
    int tid  = threadIdx.x;
    int w    = tid >> 5, lane = tid & 31;
    int gr   = lane >> 2, qc = lane & 3;
    int wm   = (w & 1) * 64;
    int wn   = (w >> 1) * 32;
    int bm   = blockIdx.x * 128;
    int bn   = blockIdx.y * 128;

    const float* ag[4]; const float* wg[4]; uint32_t soff[4];
    #pragma unroll
    for (int i = 0; i < 4; ++i) {
        int e   = tid + i * 256;
        int row = e >> 3;
        int ks4 = (e & 7) * 4;
        ag[i]   = A + (size_t)(bm + row) * DIM + ks4;
        wg[i]   = W + (size_t)(bn + row) * DIM + ks4;
        soff[i] = (uint32_t)(row * SSTR2 + ks4) * 4u;
    }

    float acc[4][4][4];
    #pragma unroll
    for (int mt = 0; mt < 4; ++mt)
        #pragma unroll
        for (int nt = 0; nt < 4; ++nt)
            #pragma unroll
            for (int i = 0; i < 4; ++i) acc[mt][nt][i] = 0.f;

    const int NC = DIM / KT;

    #pragma unroll
    for (int i = 0; i < 4; ++i) {
        cpa16(sbase + soff[i], ag[i]);
        cpa16(sbase + CH2 * 4 + soff[i], wg[i]);
    }
    CP_COMMIT();
    #pragma unroll
    for (int i = 0; i < 4; ++i) {
        cpa16(sbase + GB2 * 4 + soff[i], ag[i] + KT);
        cpa16(sbase + (GB2 + CH2) * 4 + soff[i], wg[i] + KT);
    }
    CP_COMMIT();

    int buf = 0;
    for (int c = 0; c < NC; ++c) {
        if (c + 1 < NC) CP_WAIT1(); else CP_WAIT0();
        __syncthreads();

        if (c + 2 < NC) {
            int nb = buf + 2; if (nb >= 3) nb -= 3;
            uint32_t nbb = sbase + (uint32_t)nb * GB2 * 4u;
            #pragma unroll
            for (int i = 0; i < 4; ++i) {
                cpa16(nbb + soff[i], ag[i] + (c + 2) * KT);
                cpa16(nbb + CH2 * 4 + soff[i], wg[i] + (c + 2) * KT);
            }
            CP_COMMIT();
        }

        const uint32_t* As = (const uint32_t*)(smf + buf * GB2);
        const uint32_t* Bs = As + CH2;

        #pragma unroll
        for (int ks = 0; ks < KT / 8; ++ks) {
            int k0 = ks * 8;
            uint32_t af[4][4], bf[4][2];
            #pragma unroll
            for (int mt = 0; mt < 4; ++mt) {
                const uint32_t* p = As + (wm + mt * 16 + gr) * SSTR2 + k0 + qc;
                af[mt][0] = p[0];
                af[mt][1] = p[8 * SSTR2];
                af[mt][2] = p[4];
                af[mt][3] = p[8 * SSTR2 + 4];
            }
            #pragma unroll
            for (int nt = 0; nt < 4; ++nt) {
                const uint32_t* p = Bs + (wn + nt * 8 + gr) * SSTR2 + k0 + qc;
                bf[nt][0] = p[0];
                bf[nt][1] = p[4];
            }
            #pragma unroll
            for (int mt = 0; mt < 4; ++mt)
                #pragma unroll
                for (int nt = 0; nt < 4; ++nt)
                    mma_tf32(acc[mt][nt], af[mt][0], af[mt][1], af[mt][2],
                             af[mt][3], bf[nt][0], bf[nt][1]);
        }
        if (++buf >= 3) buf -= 3;
    }

    int scol = bn + wn;
    #pragma unroll
    for (int mt = 0; mt < 4; ++mt) {
        int r0 = bm + wm + mt * 16 + gr;
        float* base = out + (size_t)r0 * DIM;
        #pragma unroll
        for (int nt = 0; nt < 4; ++nt) {
            int cb = scol + nt * 8 + 2 * qc;
            float2 bv = *(const float2*)(bias + cb);
            *(float2*)(base + cb) =
                make_float2(acc[mt][nt][0] + bv.x, acc[mt][nt][1] + bv.y);
            *(float2*)(base + 8 * DIM + cb) =
                make_float2(acc[mt][nt][2] + bv.x, acc[mt][nt][3] + bv.y);
        }
    }
}

// ---------------------------------------------------------------------------
// Flash attention: R8 structure verbatim (measured ~505us) + BIT-EXACT
// softmax fast path: when the warp-uniform running max is unchanged,
// c = ex2(0) = 1.0 exactly, so the O/l rescale is skipped (x*1.0f == x).
// ---------------------------------------------------------------------------
#define ABC  64
#define KSTR 68
#define KBUF_WORDS (64 * KSTR)
#define V_OFF   (2 * KBUF_WORDS)
#define P_OFF   (4 * KBUF_WORDS)
#define ATT_SMEM ((4 * KBUF_WORDS + 128 * KSTR) * 4)   // 104448 bytes

__global__ __launch_bounds__(256) void attn_mma()
{
    extern __shared__ float sh[];
    uint32_t sbase = smem_u32(sh);
    float* Ps = sh + P_OFF;

    int bh  = blockIdx.y;
    int q0  = blockIdx.x * 128;
    int tid = threadIdx.x;
    int w   = tid >> 5, lane = tid & 31;
    int gr  = lane >> 2, qc = lane & 3;
    int wm  = w * 16;

    const float* Qb = g_Q + ((size_t)bh * SEQ + q0) * HD;
    const float* Kb = g_K + (size_t)bh * SEQ * HD;
    const float* Vb = g_V + (size_t)bh * SEQ * HD;

    const float qs = SCALE * LOG2E;
    int r0 = wm + gr;
    uint32_t qf[8][4];
    #pragma unroll
    for (int kt = 0; kt < 8; ++kt) {
        int c = kt * 8 + qc;
        qf[kt][0] = f2tf32(Qb[(size_t)r0 * HD + c] * qs);
        qf[kt][1] = f2tf32(Qb[(size_t)(r0 + 8) * HD + c] * qs);
        qf[kt][2] = f2tf32(Qb[(size_t)r0 * HD + c + 4] * qs);
        qf[kt][3] = f2tf32(Qb[(size_t)(r0 + 8) * HD + c + 4] * qs);
    }

    const float* kg[4]; const float* vg[4]; uint32_t soff[4];
    #pragma unroll
    for (int i = 0; i < 4; ++i) {
        int slot = tid + i * 256;
        int key  = slot >> 4;
        int d4   = (slot & 15) * 4;
        kg[i]   = Kb + key * HD + d4;
        vg[i]   = Vb + key * HD + d4;
        soff[i] = (uint32_t)(key * KSTR + d4) * 4u;
    }

    float of[8][4];
    #pragma unroll
    for (int nt = 0; nt < 8; ++nt)
        #pragma unroll
        for (int i = 0; i < 4; ++i) of[nt][i] = 0.f;
    float m0 = -1e30f, m1 = -1e30f, l0 = 0.f, l1 = 0.f;

    const int NT = SEQ / ABC;   // 32

    #pragma unroll
    for (int i = 0; i < 4; ++i) {
        cpa16(sbase + soff[i], kg[i]);
        cpa16(sbase + V_OFF * 4 + soff[i], vg[i]);
    }
    CP_COMMIT();

    #pragma unroll 1
    for (int t = 0; t < NT; ++t) {
        if (t + 1 < NT) {
            uint32_t kb = sbase + (uint32_t)((t + 1) & 1) * KBUF_WORDS * 4u;
            size_t goff = (size_t)(t + 1) * ABC * HD;
            #pragma unroll
            for (int i = 0; i < 4; ++i) {
                cpa16(kb + soff[i], kg[i] + goff);
                cpa16(kb + V_OFF * 4 + soff[i], vg[i] + goff);
            }
            CP_COMMIT();
            CP_WAIT1();
        } else {
            CP_WAIT0();
        }
        __syncthreads();   // tile t visible

        const float* Kt = sh + (t & 1) * KBUF_WORDS;
        const float* Vt = Kt + V_OFF;

        // S = Q K^T  (K natural: scalar fragment gathers)
        float sf[8][4];
        #pragma unroll
        for (int nt = 0; nt < 8; ++nt)
            #pragma unroll
            for (int i = 0; i < 4; ++i) sf[nt][i] = 0.f;
        #pragma unroll
        for (int kt = 0; kt < 8; ++kt) {
            int k0 = kt * 8;
            #pragma unroll
            for (int nt = 0; nt < 8; ++nt) {
                const uint32_t* bp =
                    (const uint32_t*)(Kt + (nt * 8 + gr) * KSTR + k0 + qc);
                mma_tf32(sf[nt], qf[kt][0], qf[kt][1], qf[kt][2], qf[kt][3],
                         bp[0], bp[4]);
            }
        }

        // Online softmax (log2 domain, hardware ex2)
        float tm0 = -1e30f, tm1 = -1e30f;
        #pragma unroll
        for (int nt = 0; nt < 8; ++nt) {
            tm0 = fmaxf(tm0, fmaxf(sf[nt][0], sf[nt][1]));
            tm1 = fmaxf(tm1, fmaxf(sf[nt][2], sf[nt][3]));
        }
        tm0 = fmaxf(tm0, __shfl_xor_sync(0xffffffffu, tm0, 1));
        tm0 = fmaxf(tm0, __shfl_xor_sync(0xffffffffu, tm0, 2));
        tm1 = fmaxf(tm1, __shfl_xor_sync(0xffffffffu, tm1, 1));
        tm1 = fmaxf(tm1, __shfl_xor_sync(0xffffffffu, tm1, 2));

        // BIT-EXACT fast path: if no row in the warp has a new max, the
        // correction factor is ex2(0) == 1.0 and rescaling is the identity.
        bool noup = (tm0 <= m0) & (tm1 <= m1);
        if (!__all_sync(0xffffffffu, noup)) {
            float nm0 = fmaxf(m0, tm0), nm1 = fmaxf(m1, tm1);
            float c0 = ex2(m0 - nm0), c1 = ex2(m1 - nm1);
            m0 = nm0; m1 = nm1;
            l0 *= c0; l1 *= c1;
            #pragma unroll
            for (int nt = 0; nt < 8; ++nt) {
                of[nt][0] *= c0; of[nt][1] *= c0;
                of[nt][2] *= c1; of[nt][3] *= c1;
            }
        }

        float rs0 = 0.f, rs1 = 0.f;
        float* prow0 = Ps + (wm + gr) * KSTR + 2 * qc;
        float* prow1 = prow0 + 8 * KSTR;
        #pragma unroll
        for (int nt = 0; nt < 8; ++nt) {
            float p0 = rnaf(ex2(sf[nt][0] - m0));
            float p1 = rnaf(ex2(sf[nt][1] - m0));
            float p2 = rnaf(ex2(sf[nt][2] - m1));
            float p3 = rnaf(ex2(sf[nt][3] - m1));
            rs0 += p0 + p1;
            rs1 += p2 + p3;
            *(float2*)(prow0 + nt * 8) = make_float2(p0, p1);
            *(float2*)(prow1 + nt * 8) = make_float2(p2, p3);
        }
        rs0 += __shfl_xor_sync(0xffffffffu, rs0, 1);
        rs0 += __shfl_xor_sync(0xffffffffu, rs0, 2);
        rs1 += __shfl_xor_sync(0xffffffffu, rs1, 1);
        rs1 += __shfl_xor_sync(0xffffffffu, rs1, 2);
        l0 = l0 + rs0;
        l1 = l1 + rs1;

        __syncwarp();   // P is warp-private

        // O += P V  (V natural [key][dim]: column gathers)
        #pragma unroll
        for (int kt = 0; kt < 8; ++kt) {
            int k0 = kt * 8;
            const uint32_t* ap =
                (const uint32_t*)(Ps + (wm + gr) * KSTR + k0 + qc);
            uint32_t a0 = ap[0];
            uint32_t a1 = ap[8 * KSTR];
            uint32_t a2 = ap[4];
            uint32_t a3 = ap[8 * KSTR + 4];
            #pragma unroll
            for (int nt = 0; nt < 8; ++nt) {
                const uint32_t* vp =
                    (const uint32_t*)(Vt + (k0 + qc) * KSTR + nt * 8 + gr);
                mma_tf32(of[nt], a0, a1, a2, a3, vp[0], vp[4 * KSTR]);
            }
        }
        __syncthreads();   // buffer reads done
    }

    // Epilogue: write AO tf32-rounded, natural float2 layout (R8).
    float inv0 = 1.f / l0, inv1 = 1.f / l1;
    int b = bh / NH, h = bh % NH;
    int n0 = q0 + wm + gr;
    float* o0 = g_AO + ((size_t)(b * SEQ + n0)) * DIM + h * HD;
    float* o1 = g_AO + ((size_t)(b * SEQ + n0 + 8)) * DIM + h * HD;
    #pragma unroll
    for (int nt = 0; nt < 8; ++nt) {
        int d = nt * 8 + 2 * qc;
        *(float2*)(o0 + d) = make_float2(rnaf(of[nt][0] * inv0),
                                         rnaf(of[nt][1] * inv0));
        *(float2*)(o1 + d) = make_float2(rnaf(of[nt][2] * inv1),
                                         rnaf(of[nt][3] * inv1));
    }
}

// ---------------------------------------------------------------------------
extern "C" void kernel_launch(void* const* d_in, const int* in_sizes, int n_in,
                              void* d_out, int out_size)
{
    const float* x      = (const float*)d_in[0];
    const float* w_qkv  = (const float*)d_in[1];
    const float* w_proj = (const float*)d_in[2];
    const float* b_proj = (const float*)d_in[3];
    float* out = (float*)d_out;

    cudaFuncSetAttribute(gemm_qkv,  cudaFuncAttributeMaxDynamicSharedMemorySize, GSM1);
    cudaFuncSetAttribute(gemm_proj, cudaFuncAttributeMaxDynamicSharedMemorySize, GSM2);
    cudaFuncSetAttribute(attn_mma,  cudaFuncAttributeMaxDynamicSharedMemorySize, ATT_SMEM);

    int n8x = MROWS * DIM / 8, n8q = 3 * DIM * DIM / 8, n4p = DIM * DIM / 4;
    round_perm<<<(n8x + 255) / 256, 256>>>(x, n8x, 0);
    round_perm<<<(n8q + 255) / 256, 256>>>(w_qkv, n8q, 1);
    round_plain<<<(n4p + 255) / 256, 256>>>(w_proj, n4p);

    gemm_qkv<<<dim3(MROWS/128, 3*DIM/128), 256, GSM1>>>();
    attn_mma<<<dim3(SEQ/128, BH), 256, ATT_SMEM>>>();
    gemm_proj<<<dim3(MROWS/128, DIM/128), 256, GSM2>>>(b_proj, out);
}

// round 15
// speedup vs baseline: 1.1389x; 1.1389x over previous
#include <cuda_runtime.h>
#include <cstdint>

#define BATCH 4
#define SEQ   2048
#define DIM   768
#define NH    12
#define HD    64
#define BH    (BATCH*NH)          // 48
#define MROWS (BATCH*SEQ)         // 8192
#define SCALE 0.125f
#define LOG2E 1.4426950408889634f

// Scratch (allocation-free rule: __device__ globals)
__device__ float g_Q[BH*SEQ*HD];         // natural, fp32
__device__ float g_K[BH*SEQ*HD];         // natural, tf32
__device__ float g_V[BH*SEQ*HD];         // natural, tf32
__device__ float g_AO[BATCH*SEQ*DIM];    // natural, tf32
__device__ float g_Xr[MROWS*DIM];        // k-permuted, tf32 (GEMM1 A)
__device__ float g_Wqkvr[3*DIM*DIM];     // k-permuted, tf32 (GEMM1 B)
__device__ float g_Wprojr[DIM*DIM];      // natural, tf32   (GEMM2 B)

__device__ __forceinline__ uint32_t smem_u32(const void* p) {
    uint32_t a;
    asm("{ .reg .u64 t; cvta.to.shared.u64 t, %1; cvt.u32.u64 %0, t; }"
        : "=r"(a) : "l"(p));
    return a;
}

__device__ __forceinline__ uint32_t f2tf32(float x) {
    uint32_t r;
    asm("cvt.rna.tf32.f32 %0, %1;" : "=r"(r) : "f"(x));
    return r;
}
__device__ __forceinline__ float rnaf(float x) {
    return __uint_as_float(f2tf32(x));
}

__device__ __forceinline__ float ex2(float x) {
    float r;
    asm("ex2.approx.ftz.f32 %0, %1;" : "=f"(r) : "f"(x));
    return r;
}

__device__ __forceinline__ void cpa16(uint32_t dst, const void* src) {
    asm volatile("cp.async.cg.shared.global [%0], [%1], 16;"
                 :: "r"(dst), "l"(src));
}
#define CP_COMMIT() asm volatile("cp.async.commit_group;" ::: "memory")
#define CP_WAIT1()  asm volatile("cp.async.wait_group 1;" ::: "memory")
#define CP_WAIT0()  asm volatile("cp.async.wait_group 0;" ::: "memory")

__device__ __forceinline__ void mma_tf32(float c[4], uint32_t a0, uint32_t a1,
                                         uint32_t a2, uint32_t a3,
                                         uint32_t b0, uint32_t b1) {
    asm volatile(
        "mma.sync.aligned.m16n8k8.row.col.f32.tf32.tf32.f32 "
        "{%0,%1,%2,%3}, {%4,%5,%6,%7}, {%8,%9}, {%0,%1,%2,%3};"
        : "+f"(c[0]), "+f"(c[1]), "+f"(c[2]), "+f"(c[3])
        : "r"(a0), "r"(a1), "r"(a2), "r"(a3), "r"(b0), "r"(b1));
}

// ---------------------------------------------------------------------------
// Fused prep (one launch): tf32-round everything; k-permute x and w_qkv
// (8-group order 0,4,1,5,2,6,3,7); w_proj natural.
// Grid covers n8x + n8q + n8p groups of 8 floats.
// ---------------------------------------------------------------------------
#define N8X (MROWS*DIM/8)
#define N8Q (3*DIM*DIM/8)
#define N8P (DIM*DIM/8)

__global__ __launch_bounds__(256) void prep_all(
    const float* __restrict__ x, const float* __restrict__ wq,
    const float* __restrict__ wp)
{
    int i = blockIdx.x * 256 + threadIdx.x;
    const float* s; float* d; int idx; bool perm;
    if (i < N8X)            { s = x;  d = g_Xr;    idx = i;             perm = true; }
    else if (i < N8X + N8Q) { s = wq; d = g_Wqkvr; idx = i - N8X;       perm = true; }
    else if (i < N8X + N8Q + N8P) { s = wp; d = g_Wprojr; idx = i - N8X - N8Q; perm = false; }
    else return;

    float4 a = ((const float4*)s)[2*idx];
    float4 b = ((const float4*)s)[2*idx+1];
    float4 o0, o1;
    if (perm) {
        o0.x = rnaf(a.x); o0.y = rnaf(b.x); o0.z = rnaf(a.y); o0.w = rnaf(b.y);
        o1.x = rnaf(a.z); o1.y = rnaf(b.z); o1.z = rnaf(a.w); o1.w = rnaf(b.w);
    } else {
        o0.x = rnaf(a.x); o0.y = rnaf(a.y); o0.z = rnaf(a.z); o0.w = rnaf(a.w);
        o1.x = rnaf(b.x); o1.y = rnaf(b.y); o1.z = rnaf(b.z); o1.w = rnaf(b.w);
    }
    ((float4*)d)[2*idx]   = o0;
    ((float4*)d)[2*idx+1] = o1;
}

// ---------------------------------------------------------------------------
// GEMM1 (R13-validated, ~174us): qkv = Xr x Wqkvr. cp.async 2-stage ring,
// SSTR=40, k-permuted LDS.64 fragments. Epilogue: Q raw, K/V rounded, natural.
// ---------------------------------------------------------------------------
#define KT     32
#define SSTR1  40
#define CH1    (128 * SSTR1)
#define GB1    (2 * CH1)
#define GSM1   (2 * GB1 * 4)            // 81920

__global__ __launch_bounds__(256) void gemm_qkv()
{
    extern __shared__ float smf[];
    uint32_t sbase = smem_u32(smf);

    const float* A = g_Xr;
    const float* W = g_Wqkvr;
    int tid  = threadIdx.x;
    int w    = tid >> 5, lane = tid & 31;
    int gr   = lane >> 2, qc = lane & 3;
    int wm   = (w & 1) * 64;
    int wn   = (w >> 1) * 32;
    int bm   = blockIdx.x * 128;
    int bn   = blockIdx.y * 128;

    const float* ag[4]; const float* wg[4]; uint32_t soff[4];
    #pragma unroll
    for (int i = 0; i < 4; ++i) {
        int e   = tid + i * 256;
        int row = e >> 3;
        int ks4 = (e & 7) * 4;
        ag[i]   = A + (size_t)(bm + row) * DIM + ks4;
        wg[i]   = W + (size_t)(bn + row) * DIM + ks4;
        soff[i] = (uint32_t)(row * SSTR1 + ks4) * 4u;
    }

    float acc[4][4][4];
    #pragma unroll
    for (int mt = 0; mt < 4; ++mt)
        #pragma unroll
        for (int nt = 0; nt < 4; ++nt)
            #pragma unroll
            for (int i = 0; i < 4; ++i) acc[mt][nt][i] = 0.f;

    const int NC = DIM / KT;

    #pragma unroll
    for (int i = 0; i < 4; ++i) {
        cpa16(sbase + soff[i], ag[i]);
        cpa16(sbase + CH1 * 4 + soff[i], wg[i]);
    }
    CP_COMMIT();

    int buf = 0;
    for (int c = 0; c < NC; ++c) {
        CP_WAIT0();
        __syncthreads();

        if (c + 1 < NC) {
            uint32_t nbb = sbase + (uint32_t)(buf ^ 1) * GB1 * 4u;
            #pragma unroll
            for (int i = 0; i < 4; ++i) {
                cpa16(nbb + soff[i], ag[i] + (c + 1) * KT);
                cpa16(nbb + CH1 * 4 + soff[i], wg[i] + (c + 1) * KT);
            }
            CP_COMMIT();
        }

        const uint32_t* As = (const uint32_t*)(smf + buf * GB1);
        const uint32_t* Bs = As + CH1;

        #pragma unroll
        for (int ks = 0; ks < KT / 8; ++ks) {
            int k0 = ks * 8;
            uint32_t af[4][4], bf[4][2];
            #pragma unroll
            for (int mt = 0; mt < 4; ++mt) {
                uint2 v0 = *(const uint2*)
                    (As + (wm + mt * 16 + gr) * SSTR1 + k0 + 2 * qc);
                uint2 v1 = *(const uint2*)
                    (As + (wm + mt * 16 + 8 + gr) * SSTR1 + k0 + 2 * qc);
                af[mt][0] = v0.x; af[mt][2] = v0.y;
                af[mt][1] = v1.x; af[mt][3] = v1.y;
            }
            #pragma unroll
            for (int nt = 0; nt < 4; ++nt) {
                uint2 v = *(const uint2*)
                    (Bs + (wn + nt * 8 + gr) * SSTR1 + k0 + 2 * qc);
                bf[nt][0] = v.x; bf[nt][1] = v.y;
            }
            #pragma unroll
            for (int mt = 0; mt < 4; ++mt)
                #pragma unroll
                for (int nt = 0; nt < 4; ++nt)
                    mma_tf32(acc[mt][nt], af[mt][0], af[mt][1], af[mt][2],
                             af[mt][3], bf[nt][0], bf[nt][1]);
        }
        buf ^= 1;
    }

    int scol = bn + wn;
    int s   = scol / DIM;
    int rem = scol % DIM;
    int h   = rem / HD;
    int d0  = rem % HD;
    float* dst = (s == 0) ? g_Q : (s == 1) ? g_K : g_V;
    bool rnd = (s != 0);
    #pragma unroll
    for (int mt = 0; mt < 4; ++mt) {
        int r0 = bm + wm + mt * 16 + gr;
        int b  = r0 >> 11, n = r0 & (SEQ - 1);
        float* base = dst + ((size_t)(b * NH + h) * SEQ + n) * HD;
        #pragma unroll
        for (int nt = 0; nt < 4; ++nt) {
            int d = d0 + nt * 8 + 2 * qc;
            float v0 = acc[mt][nt][0], v1 = acc[mt][nt][1];
            float v2 = acc[mt][nt][2], v3 = acc[mt][nt][3];
            if (rnd) { v0 = rnaf(v0); v1 = rnaf(v1);
                       v2 = rnaf(v2); v3 = rnaf(v3); }
            *(float2*)(base + d) = make_float2(v0, v1);
            *(float2*)(base + 8 * HD + d) = make_float2(v2, v3);
        }
    }
}

// ---------------------------------------------------------------------------
// GEMM2 (R8-validated): out = AO x Wprojr + bias. 3-stage cp.async ring,
// SSTR=36, scalar fragment loads, natural layouts.
// ---------------------------------------------------------------------------
#define SSTR2  36
#define CH2    (128 * SSTR2)
#define GB2    (2 * CH2)
#define GSM2   (3 * GB2 * 4)            // 110592

__global__ __launch_bounds__(256) void gemm_proj(
    const float* __restrict__ bias, float* __restrict__ out)
{
    extern __shared__ float smf[];
    uint32_t sbase = smem_u32(smf);

    const float* A = g_AO;
    const float* W = g_Wprojr;
    int tid  = threadIdx.x;
    int w    = tid >> 5, lane = tid & 31;
    int gr   = lane >> 2, qc = lane & 3;
    int wm   = (w & 1) * 64;
    int wn   = (w >> 1) * 32;
    int bm   = blockIdx.x * 128;
    int bn   = blockIdx.y * 128;

    const float* ag[4]; const float* wg[4]; uint32_t soff[4];
    #pragma unroll
    for (int i = 0; i < 4; ++i) {
        int e   = tid + i * 256;
        int row = e >> 3;
        int ks4 = (e & 7) * 4;
        ag[i]   = A + (size_t)(bm + row) * DIM + ks4;
        wg[i]   = W + (size_t)(bn + row) * DIM + ks4;
        soff[i] = (uint32_t)(row * SSTR2 + ks4) * 4u;
    }

    float acc[4][4][4];
    #pragma unroll
    for (int mt = 0; mt < 4; ++mt)
        #pragma unroll
        for (int nt = 0; nt < 4; ++nt)
            #pragma unroll
            for (int i = 0; i < 4; ++i) acc[mt][nt][i] = 0.f;

    const int NC = DIM / KT;

    #pragma unroll
    for (int i = 0; i < 4; ++i) {
        cpa16(sbase + soff[i], ag[i]);
        cpa16(sbase + CH2 * 4 + soff[i], wg[i]);
    }
    CP_COMMIT();
    #pragma unroll
    for (int i = 0; i < 4; ++i) {
        cpa16(sbase + GB2 * 4 + soff[i], ag[i] + KT);
        cpa16(sbase + (GB2 + CH2) * 4 + soff[i], wg[i] + KT);
    }
    CP_COMMIT();

    int buf = 0;
    for (int c = 0; c < NC; ++c) {
        if (c + 1 < NC) CP_WAIT1(); else CP_WAIT0();
        __syncthreads();

        if (c + 2 < NC) {
            int nb = buf + 2; if (nb >= 3) nb -= 3;
            uint32_t nbb = sbase + (uint32_t)nb * GB2 * 4u;
            #pragma unroll
            for (int i = 0; i < 4; ++i) {
                cpa16(nbb + soff[i], ag[i] + (c + 2) * KT);
                cpa16(nbb + CH2 * 4 + soff[i], wg[i] + (c + 2) * KT);
            }
            CP_COMMIT();
        }

        const uint32_t* As = (const uint32_t*)(smf + buf * GB2);
        const uint32_t* Bs = As + CH2;

        #pragma unroll
        for (int ks = 0; ks < KT / 8; ++ks) {
            int k0 = ks * 8;
            uint32_t af[4][4], bf[4][2];
            #pragma unroll
            for (int mt = 0; mt < 4; ++mt) {
                const uint32_t* p = As + (wm + mt * 16 + gr) * SSTR2 + k0 + qc;
                af[mt][0] = p[0];
                af[mt][1] = p[8 * SSTR2];
                af[mt][2] = p[4];
                af[mt][3] = p[8 * SSTR2 + 4];
            }
            #pragma unroll
            for (int nt = 0; nt < 4; ++nt) {
                const uint32_t* p = Bs + (wn + nt * 8 + gr) * SSTR2 + k0 + qc;
                bf[nt][0] = p[0];
                bf[nt][1] = p[4];
            }
            #pragma unroll
            for (int mt = 0; mt < 4; ++mt)
                #pragma unroll
                for (int nt = 0; nt < 4; ++nt)
                    mma_tf32(acc[mt][nt], af[mt][0], af[mt][1], af[mt][2],
                             af[mt][3], bf[nt][0], bf[nt][1]);
        }
        if (++buf >= 3) buf -= 3;
    }

    int scol = bn + wn;
    #pragma unroll
    for (int mt = 0; mt < 4; ++mt) {
        int r0 = bm + wm + mt * 16 + gr;
        float* base = out + (size_t)r0 * DIM;
        #pragma unroll
        for (int nt = 0; nt < 4; ++nt) {
            int cb = scol + nt * 8 + 2 * qc;
            float2 bv = *(const float2*)(bias + cb);
            *(float2*)(base + cb) =
                make_float2(acc[mt][nt][0] + bv.x, acc[mt][nt][1] + bv.y);
            *(float2*)(base + 8 * DIM + cb) =
                make_float2(acc[mt][nt][2] + bv.x, acc[mt][nt][3] + bv.y);
        }
    }
}

// ---------------------------------------------------------------------------
// Flash attention: exact R8 arithmetic & structure (best measured, ~505us).
// ---------------------------------------------------------------------------
#define ABC  64
#define KSTR 68
#define KBUF_WORDS (64 * KSTR)
#define V_OFF   (2 * KBUF_WORDS)
#define P_OFF   (4 * KBUF_WORDS)
#define ATT_SMEM ((4 * KBUF_WORDS + 128 * KSTR) * 4)   // 104448 bytes

__global__ __launch_bounds__(256) void attn_mma()
{
    extern __shared__ float sh[];
    uint32_t sbase = smem_u32(sh);
    float* Ps = sh + P_OFF;

    int bh  = blockIdx.y;
    int q0  = blockIdx.x * 128;
    int tid = threadIdx.x;
    int w   = tid >> 5, lane = tid & 31;
    int gr  = lane >> 2, qc = lane & 3;
    int wm  = w * 16;

    const float* Qb = g_Q + ((size_t)bh * SEQ + q0) * HD;
    const float* Kb = g_K + (size_t)bh * SEQ * HD;
    const float* Vb = g_V + (size_t)bh * SEQ * HD;

    const float qs = SCALE * LOG2E;
    int r0 = wm + gr;
    uint32_t qf[8][4];
    #pragma unroll
    for (int kt = 0; kt < 8; ++kt) {
        int c = kt * 8 + qc;
        qf[kt][0] = f2tf32(Qb[(size_t)r0 * HD + c] * qs);
        qf[kt][1] = f2tf32(Qb[(size_t)(r0 + 8) * HD + c] * qs);
        qf[kt][2] = f2tf32(Qb[(size_t)r0 * HD + c + 4] * qs);
        qf[kt][3] = f2tf32(Qb[(size_t)(r0 + 8) * HD + c + 4] * qs);
    }

    const float* kg[4]; const float* vg[4]; uint32_t soff[4];
    #pragma unroll
    for (int i = 0; i < 4; ++i) {
        int slot = tid + i * 256;
        int key  = slot >> 4;
        int d4   = (slot & 15) * 4;
        kg[i]   = Kb + key * HD + d4;
        vg[i]   = Vb + key * HD + d4;
        soff[i] = (uint32_t)(key * KSTR + d4) * 4u;
    }

    float of[8][4];
    #pragma unroll
    for (int nt = 0; nt < 8; ++nt)
        #pragma unroll
        for (int i = 0; i < 4; ++i) of[nt][i] = 0.f;
    float m0 = -1e30f, m1 = -1e30f, l0 = 0.f, l1 = 0.f;

    const int NT = SEQ / ABC;   // 32

    #pragma unroll
    for (int i = 0; i < 4; ++i) {
        cpa16(sbase + soff[i], kg[i]);
        cpa16(sbase + V_OFF * 4 + soff[i], vg[i]);
    }
    CP_COMMIT();

    #pragma unroll 1
    for (int t = 0; t < NT; ++t) {
        if (t + 1 < NT) {
            uint32_t kb = sbase + (uint32_t)((t + 1) & 1) * KBUF_WORDS * 4u;
            size_t goff = (size_t)(t + 1) * ABC * HD;
            #pragma unroll
            for (int i = 0; i < 4; ++i) {
                cpa16(kb + soff[i], kg[i] + goff);
                cpa16(kb + V_OFF * 4 + soff[i], vg[i] + goff);
            }
            CP_COMMIT();
            CP_WAIT1();
        } else {
            CP_WAIT0();
        }
        __syncthreads();   // tile t visible

        const float* Kt = sh + (t & 1) * KBUF_WORDS;
        const float* Vt = Kt + V_OFF;

        // S = Q K^T
        float sf[8][4];
        #pragma unroll
        for (int nt = 0; nt < 8; ++nt)
            #pragma unroll
            for (int i = 0; i < 4; ++i) sf[nt][i] = 0.f;
        #pragma unroll
        for (int kt = 0; kt < 8; ++kt) {
            int k0 = kt * 8;
            #pragma unroll
            for (int nt = 0; nt < 8; ++nt) {
                const uint32_t* bp =
                    (const uint32_t*)(Kt + (nt * 8 + gr) * KSTR + k0 + qc);
                mma_tf32(sf[nt], qf[kt][0], qf[kt][1], qf[kt][2], qf[kt][3],
                         bp[0], bp[4]);
            }
        }

        // Online softmax (log2 domain, hardware ex2) — R8 arithmetic exactly
        float tm0 = -1e30f, tm1 = -1e30f;
        #pragma unroll
        for (int nt = 0; nt < 8; ++nt) {
            tm0 = fmaxf(tm0, fmaxf(sf[nt][0], sf[nt][1]));
            tm1 = fmaxf(tm1, fmaxf(sf[nt][2], sf[nt][3]));
        }
        tm0 = fmaxf(tm0, __shfl_xor_sync(0xffffffffu, tm0, 1));
        tm0 = fmaxf(tm0, __shfl_xor_sync(0xffffffffu, tm0, 2));
        tm1 = fmaxf(tm1, __shfl_xor_sync(0xffffffffu, tm1, 1));
        tm1 = fmaxf(tm1, __shfl_xor_sync(0xffffffffu, tm1, 2));

        float nm0 = fmaxf(m0, tm0), nm1 = fmaxf(m1, tm1);
        float c0 = ex2(m0 - nm0), c1 = ex2(m1 - nm1);
        m0 = nm0; m1 = nm1;

        float rs0 = 0.f, rs1 = 0.f;
        float* prow0 = Ps + (wm + gr) * KSTR + 2 * qc;
        float* prow1 = prow0 + 8 * KSTR;
        #pragma unroll
        for (int nt = 0; nt < 8; ++nt) {
            float p0 = rnaf(ex2(sf[nt][0] - nm0));
            float p1 = rnaf(ex2(sf[nt][1] - nm0));
            float p2 = rnaf(ex2(sf[nt][2] - nm1));
            float p3 = rnaf(ex2(sf[nt][3] - nm1));
            rs0 += p0 + p1;
            rs1 += p2 + p3;
            *(float2*)(prow0 + nt * 8) = make_float2(p0, p1);
            *(float2*)(prow1 + nt * 8) = make_float2(p2, p3);
        }
        rs0 += __shfl_xor_sync(0xffffffffu, rs0, 1);
        rs0 += __shfl_xor_sync(0xffffffffu, rs0, 2);
        rs1 += __shfl_xor_sync(0xffffffffu, rs1, 1);
        rs1 += __shfl_xor_sync(0xffffffffu, rs1, 2);
        l0 = l0 * c0 + rs0;
        l1 = l1 * c1 + rs1;

        #pragma unroll
        for (int nt = 0; nt < 8; ++nt) {
            of[nt][0] *= c0; of[nt][1] *= c0;
            of[nt][2] *= c1; of[nt][3] *= c1;
        }
        __syncwarp();   // P is warp-private

        // O += P V
        #pragma unroll
        for (int kt = 0; kt < 8; ++kt) {
            int k0 = kt * 8;
            const uint32_t* ap =
                (const uint32_t*)(Ps + (wm + gr) * KSTR + k0 + qc);
            uint32_t a0 = ap[0];
            uint32_t a1 = ap[8 * KSTR];
            uint32_t a2 = ap[4];
            uint32_t a3 = ap[8 * KSTR + 4];
            #pragma unroll
            for (int nt = 0; nt < 8; ++nt) {
                const uint32_t* vp =
                    (const uint32_t*)(Vt + (k0 + qc) * KSTR + nt * 8 + gr);
                mma_tf32(of[nt], a0, a1, a2, a3, vp[0], vp[4 * KSTR]);
            }
        }
        __syncthreads();   // buffer reads done
    }

    // Epilogue: write AO tf32-rounded, natural float2 layout.
    float inv0 = 1.f / l0, inv1 = 1.f / l1;
    int b = bh / NH, h = bh % NH;
    int n0 = q0 + wm + gr;
    float* o0 = g_AO + ((size_t)(b * SEQ + n0)) * DIM + h * HD;
    float* o1 = g_AO + ((size_t)(b * SEQ + n0 + 8)) * DIM + h * HD;
    #pragma unroll
    for (int nt = 0; nt < 8; ++nt) {
        int d = nt * 8 + 2 * qc;
        *(float2*)(o0 + d) = make_float2(rnaf(of[nt][0] * inv0),
                                         rnaf(of[nt][1] * inv0));
        *(float2*)(o1 + d) = make_float2(rnaf(of[nt][2] * inv1),
                                         rnaf(of[nt][3] * inv1));
    }
}

// ---------------------------------------------------------------------------
extern "C" void kernel_launch(void* const* d_in, const int* in_sizes, int n_in,
                              void* d_out, int out_size)
{
    const float* x      = (const float*)d_in[0];
    const float* w_qkv  = (const float*)d_in[1];
    const float* w_proj = (const float*)d_in[2];
    const float* b_proj = (const float*)d_in[3];
    float* out = (float*)d_out;

    cudaFuncSetAttribute(gemm_qkv,  cudaFuncAttributeMaxDynamicSharedMemorySize, GSM1);
    cudaFuncSetAttribute(gemm_proj, cudaFuncAttributeMaxDynamicSharedMemorySize, GSM2);
    cudaFuncSetAttribute(attn_mma,  cudaFuncAttributeMaxDynamicSharedMemorySize, ATT_SMEM);

    int n8 = N8X + N8Q + N8P;
    prep_all<<<(n8 + 255) / 256, 256>>>(x, w_qkv, w_proj);

    gemm_qkv<<<dim3(MROWS/128, 3*DIM/128), 256, GSM1>>>();
    attn_mma<<<dim3(SEQ/128, BH), 256, ATT_SMEM>>>();
    gemm_proj<<<dim3(MROWS/128, DIM/128), 256, GSM2>>>(b_proj, out);
}

// round 16
// speedup vs baseline: 1.1390x; 1.0001x over previous
#include <cuda_runtime.h>
#include <cstdint>

#define BATCH 4
#define SEQ   2048
#define DIM   768
#define NH    12
#define HD    64
#define BH    (BATCH*NH)          // 48
#define MROWS (BATCH*SEQ)         // 8192
#define SCALE 0.125f
#define LOG2E 1.4426950408889634f

// Scratch (allocation-free rule: __device__ globals)
__device__ float g_Q[BH*SEQ*HD];         // natural, fp32
__device__ float g_K[BH*SEQ*HD];         // natural, tf32
__device__ float g_V[BH*SEQ*HD];         // natural, tf32
__device__ float g_AO[BATCH*SEQ*DIM];    // natural, tf32
__device__ float g_Xr[MROWS*DIM];        // k-permuted, tf32 (GEMM1 A)
__device__ float g_Wqkvr[3*DIM*DIM];     // k-permuted, tf32 (GEMM1 B)
__device__ float g_Wprojr[DIM*DIM];      // natural, tf32   (GEMM2 B)

__device__ __forceinline__ uint32_t smem_u32(const void* p) {
    uint32_t a;
    asm("{ .reg .u64 t; cvta.to.shared.u64 t, %1; cvt.u32.u64 %0, t; }"
        : "=r"(a) : "l"(p));
    return a;
}

__device__ __forceinline__ uint32_t f2tf32(float x) {
    uint32_t r;
    asm("cvt.rna.tf32.f32 %0, %1;" : "=r"(r) : "f"(x));
    return r;
}
__device__ __forceinline__ float rnaf(float x) {
    return __uint_as_float(f2tf32(x));
}

__device__ __forceinline__ float ex2(float x) {
    float r;
    asm("ex2.approx.ftz.f32 %0, %1;" : "=f"(r) : "f"(x));
    return r;
}

__device__ __forceinline__ void cpa16(uint32_t dst, const void* src) {
    asm volatile("cp.async.cg.shared.global [%0], [%1], 16;"
                 :: "r"(dst), "l"(src));
}
#define CP_COMMIT() asm volatile("cp.async.commit_group;" ::: "memory")
#define CP_WAIT1()  asm volatile("cp.async.wait_group 1;" ::: "memory")
#define CP_WAIT0()  asm volatile("cp.async.wait_group 0;" ::: "memory")

__device__ __forceinline__ void mma_tf32(float c[4], uint32_t a0, uint32_t a1,
                                         uint32_t a2, uint32_t a3,
                                         uint32_t b0, uint32_t b1) {
    asm volatile(
        "mma.sync.aligned.m16n8k8.row.col.f32.tf32.tf32.f32 "
        "{%0,%1,%2,%3}, {%4,%5,%6,%7}, {%8,%9}, {%0,%1,%2,%3};"
        : "+f"(c[0]), "+f"(c[1]), "+f"(c[2]), "+f"(c[3])
        : "r"(a0), "r"(a1), "r"(a2), "r"(a3), "r"(b0), "r"(b1));
}

// ---------------------------------------------------------------------------
// Fused prep (one launch): tf32-round everything; k-permute x and w_qkv
// (8-group order 0,4,1,5,2,6,3,7); w_proj natural.
// Grid covers n8x + n8q + n8p groups of 8 floats.
// ---------------------------------------------------------------------------
#define N8X (MROWS*DIM/8)
#define N8Q (3*DIM*DIM/8)
#define N8P (DIM*DIM/8)

__global__ __launch_bounds__(256) void prep_all(
    const float* __restrict__ x, const float* __restrict__ wq,
    const float* __restrict__ wp)
{
    int i = blockIdx.x * 256 + threadIdx.x;
    const float* s; float* d; int idx; bool perm;
    if (i < N8X)            { s = x;  d = g_Xr;    idx = i;             perm = true; }
    else if (i < N8X + N8Q) { s = wq; d = g_Wqkvr; idx = i - N8X;       perm = true; }
    else if (i < N8X + N8Q + N8P) { s = wp; d = g_Wprojr; idx = i - N8X - N8Q; perm = false; }
    else return;

    float4 a = ((const float4*)s)[2*idx];
    float4 b = ((const float4*)s)[2*idx+1];
    float4 o0, o1;
    if (perm) {
        o0.x = rnaf(a.x); o0.y = rnaf(b.x); o0.z = rnaf(a.y); o0.w = rnaf(b.y);
        o1.x = rnaf(a.z); o1.y = rnaf(b.z); o1.z = rnaf(a.w); o1.w = rnaf(b.w);
    } else {
        o0.x = rnaf(a.x); o0.y = rnaf(a.y); o0.z = rnaf(a.z); o0.w = rnaf(a.w);
        o1.x = rnaf(b.x); o1.y = rnaf(b.y); o1.z = rnaf(b.z); o1.w = rnaf(b.w);
    }
    ((float4*)d)[2*idx]   = o0;
    ((float4*)d)[2*idx+1] = o1;
}

// ---------------------------------------------------------------------------
// GEMM1 (R13-validated, ~174us): qkv = Xr x Wqkvr. cp.async 2-stage ring,
// SSTR=40, k-permuted LDS.64 fragments. Epilogue: Q raw, K/V rounded, natural.
// ---------------------------------------------------------------------------
#define KT     32
#define SSTR1  40
#define CH1    (128 * SSTR1)
#define GB1    (2 * CH1)
#define GSM1   (2 * GB1 * 4)            // 81920

__global__ __launch_bounds__(256) void gemm_qkv()
{
    extern __shared__ float smf[];
    uint32_t sbase = smem_u32(smf);

    const float* A = g_Xr;
    const float* W = g_Wqkvr;
    int tid  = threadIdx.x;
    int w    = tid >> 5, lane = tid & 31;
    int gr   = lane >> 2, qc = lane & 3;
    int wm   = (w & 1) * 64;
    int wn   = (w >> 1) * 32;
    int bm   = blockIdx.x * 128;
    int bn   = blockIdx.y * 128;

    const float* ag[4]; const float* wg[4]; uint32_t soff[4];
    #pragma unroll
    for (int i = 0; i < 4; ++i) {
        int e   = tid + i * 256;
        int row = e >> 3;
        int ks4 = (e & 7) * 4;
        ag[i]   = A + (size_t)(bm + row) * DIM + ks4;
        wg[i]   = W + (size_t)(bn + row) * DIM + ks4;
        soff[i] = (uint32_t)(row * SSTR1 + ks4) * 4u;
    }

    float acc[4][4][4];
    #pragma unroll
    for (int mt = 0; mt < 4; ++mt)
        #pragma unroll
        for (int nt = 0; nt < 4; ++nt)
            #pragma unroll
            for (int i = 0; i < 4; ++i) acc[mt][nt][i] = 0.f;

    const int NC = DIM / KT;

    #pragma unroll
    for (int i = 0; i < 4; ++i) {
        cpa16(sbase + soff[i], ag[i]);
        cpa16(sbase + CH1 * 4 + soff[i], wg[i]);
    }
    CP_COMMIT();

    int buf = 0;
    for (int c = 0; c < NC; ++c) {
        CP_WAIT0();
        __syncthreads();

        if (c + 1 < NC) {
            uint32_t nbb = sbase + (uint32_t)(buf ^ 1) * GB1 * 4u;
            #pragma unroll
            for (int i = 0; i < 4; ++i) {
                cpa16(nbb + soff[i], ag[i] + (c + 1) * KT);
                cpa16(nbb + CH1 * 4 + soff[i], wg[i] + (c + 1) * KT);
            }
            CP_COMMIT();
        }

        const uint32_t* As = (const uint32_t*)(smf + buf * GB1);
        const uint32_t* Bs = As + CH1;

        #pragma unroll
        for (int ks = 0; ks < KT / 8; ++ks) {
            int k0 = ks * 8;
            uint32_t af[4][4], bf[4][2];
            #pragma unroll
            for (int mt = 0; mt < 4; ++mt) {
                uint2 v0 = *(const uint2*)
                    (As + (wm + mt * 16 + gr) * SSTR1 + k0 + 2 * qc);
                uint2 v1 = *(const uint2*)
                    (As + (wm + mt * 16 + 8 + gr) * SSTR1 + k0 + 2 * qc);
                af[mt][0] = v0.x; af[mt][2] = v0.y;
                af[mt][1] = v1.x; af[mt][3] = v1.y;
            }
            #pragma unroll
            for (int nt = 0; nt < 4; ++nt) {
                uint2 v = *(const uint2*)
                    (Bs + (wn + nt * 8 + gr) * SSTR1 + k0 + 2 * qc);
                bf[nt][0] = v.x; bf[nt][1] = v.y;
            }
            #pragma unroll
            for (int mt = 0; mt < 4; ++mt)
                #pragma unroll
                for (int nt = 0; nt < 4; ++nt)
                    mma_tf32(acc[mt][nt], af[mt][0], af[mt][1], af[mt][2],
                             af[mt][3], bf[nt][0], bf[nt][1]);
        }
        buf ^= 1;
    }

    int scol = bn + wn;
    int s   = scol / DIM;
    int rem = scol % DIM;
    int h   = rem / HD;
    int d0  = rem % HD;
    float* dst = (s == 0) ? g_Q : (s == 1) ? g_K : g_V;
    bool rnd = (s != 0);
    #pragma unroll
    for (int mt = 0; mt < 4; ++mt) {
        int r0 = bm + wm + mt * 16 + gr;
        int b  = r0 >> 11, n = r0 & (SEQ - 1);
        float* base = dst + ((size_t)(b * NH + h) * SEQ + n) * HD;
        #pragma unroll
        for (int nt = 0; nt < 4; ++nt) {
            int d = d0 + nt * 8 + 2 * qc;
            float v0 = acc[mt][nt][0], v1 = acc[mt][nt][1];
            float v2 = acc[mt][nt][2], v3 = acc[mt][nt][3];
            if (rnd) { v0 = rnaf(v0); v1 = rnaf(v1);
                       v2 = rnaf(v2); v3 = rnaf(v3); }
            *(float2*)(base + d) = make_float2(v0, v1);
            *(float2*)(base + 8 * HD + d) = make_float2(v2, v3);
        }
    }
}

// ---------------------------------------------------------------------------
// GEMM2 (R8-validated): out = AO x Wprojr + bias. 3-stage cp.async ring,
// SSTR=36, scalar fragment loads, natural layouts.
// ---------------------------------------------------------------------------
#define SSTR2  36
#define CH2    (128 * SSTR2)
#define GB2    (2 * CH2)
#define GSM2   (3 * GB2 * 4)            // 110592

__global__ __launch_bounds__(256) void gemm_proj(
    const float* __restrict__ bias, float* __restrict__ out)
{
    extern __shared__ float smf[];
    uint32_t sbase = smem_u32(smf);

    const float* A = g_AO;
    const float* W = g_Wprojr;
    int tid  = threadIdx.x;
    int w    = tid >> 5, lane = tid & 31;
    int gr   = lane >> 2, qc = lane & 3;
    int wm   = (w & 1) * 64;
    int wn   = (w >> 1) * 32;
    int bm   = blockIdx.x * 128;
    int bn   = blockIdx.y * 128;

    const float* ag[4]; const float* wg[4]; uint32_t soff[4];
    #pragma unroll
    for (int i = 0; i < 4; ++i) {
        int e   = tid + i * 256;
        int row = e >> 3;
        int ks4 = (e & 7) * 4;
        ag[i]   = A + (size_t)(bm + row) * DIM + ks4;
        wg[i]   = W + (size_t)(bn + row) * DIM + ks4;
        soff[i] = (uint32_t)(row * SSTR2 + ks4) * 4u;
    }

    float acc[4][4][4];
    #pragma unroll
    for (int mt = 0; mt < 4; ++mt)
        #pragma unroll
        for (int nt = 0; nt < 4; ++nt)
            #pragma unroll
            for (int i = 0; i < 4; ++i) acc[mt][nt][i] = 0.f;

    const int NC = DIM / KT;

    #pragma unroll
    for (int i = 0; i < 4; ++i) {
        cpa16(sbase + soff[i], ag[i]);
        cpa16(sbase + CH2 * 4 + soff[i], wg[i]);
    }
    CP_COMMIT();
    #pragma unroll
    for (int i = 0; i < 4; ++i) {
        cpa16(sbase + GB2 * 4 + soff[i], ag[i] + KT);
        cpa16(sbase + (GB2 + CH2) * 4 + soff[i], wg[i] + KT);
    }
    CP_COMMIT();

    int buf = 0;
    for (int c = 0; c < NC; ++c) {
        if (c + 1 < NC) CP_WAIT1(); else CP_WAIT0();
        __syncthreads();

        if (c + 2 < NC) {
            int nb = buf + 2; if (nb >= 3) nb -= 3;
            uint32_t nbb = sbase + (uint32_t)nb * GB2 * 4u;
            #pragma unroll
            for (int i = 0; i < 4; ++i) {
                cpa16(nbb + soff[i], ag[i] + (c + 2) * KT);
                cpa16(nbb + CH2 * 4 + soff[i], wg[i] + (c + 2) * KT);
            }
            CP_COMMIT();
        }

        const uint32_t* As = (const uint32_t*)(smf + buf * GB2);
        const uint32_t* Bs = As + CH2;

        #pragma unroll
        for (int ks = 0; ks < KT / 8; ++ks) {
            int k0 = ks * 8;
            uint32_t af[4][4], bf[4][2];
            #pragma unroll
            for (int mt = 0; mt < 4; ++mt) {
                const uint32_t* p = As + (wm + mt * 16 + gr) * SSTR2 + k0 + qc;
                af[mt][0] = p[0];
                af[mt][1] = p[8 * SSTR2];
                af[mt][2] = p[4];
                af[mt][3] = p[8 * SSTR2 + 4];
            }
            #pragma unroll
            for (int nt = 0; nt < 4; ++nt) {
                const uint32_t* p = Bs + (wn + nt * 8 + gr) * SSTR2 + k0 + qc;
                bf[nt][0] = p[0];
                bf[nt][1] = p[4];
            }
            #pragma unroll
            for (int mt = 0; mt < 4; ++mt)
                #pragma unroll
                for (int nt = 0; nt < 4; ++nt)
                    mma_tf32(acc[mt][nt], af[mt][0], af[mt][1], af[mt][2],
                             af[mt][3], bf[nt][0], bf[nt][1]);
        }
        if (++buf >= 3) buf -= 3;
    }

    int scol = bn + wn;
    #pragma unroll
    for (int mt = 0; mt < 4; ++mt) {
        int r0 = bm + wm + mt * 16 + gr;
        float* base = out + (size_t)r0 * DIM;
        #pragma unroll
        for (int nt = 0; nt < 4; ++nt) {
            int cb = scol + nt * 8 + 2 * qc;
            float2 bv = *(const float2*)(bias + cb);
            *(float2*)(base + cb) =
                make_float2(acc[mt][nt][0] + bv.x, acc[mt][nt][1] + bv.y);
            *(float2*)(base + 8 * DIM + cb) =
                make_float2(acc[mt][nt][2] + bv.x, acc[mt][nt][3] + bv.y);
        }
    }
}

// ---------------------------------------------------------------------------
// Flash attention: exact R8 arithmetic & structure (best measured, ~505us).
// ---------------------------------------------------------------------------
#define ABC  64
#define KSTR 68
#define KBUF_WORDS (64 * KSTR)
#define V_OFF   (2 * KBUF_WORDS)
#define P_OFF   (4 * KBUF_WORDS)
#define ATT_SMEM ((4 * KBUF_WORDS + 128 * KSTR) * 4)   // 104448 bytes

__global__ __launch_bounds__(256) void attn_mma()
{
    extern __shared__ float sh[];
    uint32_t sbase = smem_u32(sh);
    float* Ps = sh + P_OFF;

    int bh  = blockIdx.y;
    int q0  = blockIdx.x * 128;
    int tid = threadIdx.x;
    int w   = tid >> 5, lane = tid & 31;
    int gr  = lane >> 2, qc = lane & 3;
    int wm  = w * 16;

    const float* Qb = g_Q + ((size_t)bh * SEQ + q0) * HD;
    const float* Kb = g_K + (size_t)bh * SEQ * HD;
    const float* Vb = g_V + (size_t)bh * SEQ * HD;

    const float qs = SCALE * LOG2E;
    int r0 = wm + gr;
    uint32_t qf[8][4];
    #pragma unroll
    for (int kt = 0; kt < 8; ++kt) {
        int c = kt * 8 + qc;
        qf[kt][0] = f2tf32(Qb[(size_t)r0 * HD + c] * qs);
        qf[kt][1] = f2tf32(Qb[(size_t)(r0 + 8) * HD + c] * qs);
        qf[kt][2] = f2tf32(Qb[(size_t)r0 * HD + c + 4] * qs);
        qf[kt][3] = f2tf32(Qb[(size_t)(r0 + 8) * HD + c + 4] * qs);
    }

    const float* kg[4]; const float* vg[4]; uint32_t soff[4];
    #pragma unroll
    for (int i = 0; i < 4; ++i) {
        int slot = tid + i * 256;
        int key  = slot >> 4;
        int d4   = (slot & 15) * 4;
        kg[i]   = Kb + key * HD + d4;
        vg[i]   = Vb + key * HD + d4;
        soff[i] = (uint32_t)(key * KSTR + d4) * 4u;
    }

    float of[8][4];
    #pragma unroll
    for (int nt = 0; nt < 8; ++nt)
        #pragma unroll
        for (int i = 0; i < 4; ++i) of[nt][i] = 0.f;
    float m0 = -1e30f, m1 = -1e30f, l0 = 0.f, l1 = 0.f;

    const int NT = SEQ / ABC;   // 32

    #pragma unroll
    for (int i = 0; i < 4; ++i) {
        cpa16(sbase + soff[i], kg[i]);
        cpa16(sbase + V_OFF * 4 + soff[i], vg[i]);
    }
    CP_COMMIT();

    #pragma unroll 1
    for (int t = 0; t < NT; ++t) {
        if (t + 1 < NT) {
            uint32_t kb = sbase + (uint32_t)((t + 1) & 1) * KBUF_WORDS * 4u;
            size_t goff = (size_t)(t + 1) * ABC * HD;
            #pragma unroll
            for (int i = 0; i < 4; ++i) {
                cpa16(kb + soff[i], kg[i] + goff);
                cpa16(kb + V_OFF * 4 + soff[i], vg[i] + goff);
            }
            CP_COMMIT();
            CP_WAIT1();
        } else {
            CP_WAIT0();
        }
        __syncthreads();   // tile t visible

        const float* Kt = sh + (t & 1) * KBUF_WORDS;
        const float* Vt = Kt + V_OFF;

        // S = Q K^T
        float sf[8][4];
        #pragma unroll
        for (int nt = 0; nt < 8; ++nt)
            #pragma unroll
            for (int i = 0; i < 4; ++i) sf[nt][i] = 0.f;
        #pragma unroll
        for (int kt = 0; kt < 8; ++kt) {
            int k0 = kt * 8;
            #pragma unroll
            for (int nt = 0; nt < 8; ++nt) {
                const uint32_t* bp =
                    (const uint32_t*)(Kt + (nt * 8 + gr) * KSTR + k0 + qc);
                mma_tf32(sf[nt], qf[kt][0], qf[kt][1], qf[kt][2], qf[kt][3],
                         bp[0], bp[4]);
            }
        }

        // Online softmax (log2 domain, hardware ex2) — R8 arithmetic exactly
        float tm0 = -1e30f, tm1 = -1e30f;
        #pragma unroll
        for (int nt = 0; nt < 8; ++nt) {
            tm0 = fmaxf(tm0, fmaxf(sf[nt][0], sf[nt][1]));
            tm1 = fmaxf(tm1, fmaxf(sf[nt][2], sf[nt][3]));
        }
        tm0 = fmaxf(tm0, __shfl_xor_sync(0xffffffffu, tm0, 1));
        tm0 = fmaxf(tm0, __shfl_xor_sync(0xffffffffu, tm0, 2));
        tm1 = fmaxf(tm1, __shfl_xor_sync(0xffffffffu, tm1, 1));
        tm1 = fmaxf(tm1, __shfl_xor_sync(0xffffffffu, tm1, 2));

        float nm0 = fmaxf(m0, tm0), nm1 = fmaxf(m1, tm1);
        float c0 = ex2(m0 - nm0), c1 = ex2(m1 - nm1);
        m0 = nm0; m1 = nm1;

        float rs0 = 0.f, rs1 = 0.f;
        float* prow0 = Ps + (wm + gr) * KSTR + 2 * qc;
        float* prow1 = prow0 + 8 * KSTR;
        #pragma unroll
        for (int nt = 0; nt < 8; ++nt) {
            float p0 = rnaf(ex2(sf[nt][0] - nm0));
            float p1 = rnaf(ex2(sf[nt][1] - nm0));
            float p2 = rnaf(ex2(sf[nt][2] - nm1));
            float p3 = rnaf(ex2(sf[nt][3] - nm1));
            rs0 += p0 + p1;
            rs1 += p2 + p3;
            *(float2*)(prow0 + nt * 8) = make_float2(p0, p1);
            *(float2*)(prow1 + nt * 8) = make_float2(p2, p3);
        }
        rs0 += __shfl_xor_sync(0xffffffffu, rs0, 1);
        rs0 += __shfl_xor_sync(0xffffffffu, rs0, 2);
        rs1 += __shfl_xor_sync(0xffffffffu, rs1, 1);
        rs1 += __shfl_xor_sync(0xffffffffu, rs1, 2);
        l0 = l0 * c0 + rs0;
        l1 = l1 * c1 + rs1;

        #pragma unroll
        for (int nt = 0; nt < 8; ++nt) {
            of[nt][0] *= c0; of[nt][1] *= c0;
            of[nt][2] *= c1; of[nt][3] *= c1;
        }
        __syncwarp();   // P is warp-private

        // O += P V
        #pragma unroll
        for (int kt = 0; kt < 8; ++kt) {
            int k0 = kt * 8;
            const uint32_t* ap =
                (const uint32_t*)(Ps + (wm + gr) * KSTR + k0 + qc);
            uint32_t a0 = ap[0];
            uint32_t a1 = ap[8 * KSTR];
            uint32_t a2 = ap[4];
            uint32_t a3 = ap[8 * KSTR + 4];
            #pragma unroll
            for (int nt = 0; nt < 8; ++nt) {
                const uint32_t* vp =
                    (const uint32_t*)(Vt + (k0 + qc) * KSTR + nt * 8 + gr);
                mma_tf32(of[nt], a0, a1, a2, a3, vp[0], vp[4 * KSTR]);
            }
        }
        __syncthreads();   // buffer reads done
    }

    // Epilogue: write AO tf32-rounded, natural float2 layout.
    float inv0 = 1.f / l0, inv1 = 1.f / l1;
    int b = bh / NH, h = bh % NH;
    int n0 = q0 + wm + gr;
    float* o0 = g_AO + ((size_t)(b * SEQ + n0)) * DIM + h * HD;
    float* o1 = g_AO + ((size_t)(b * SEQ + n0 + 8)) * DIM + h * HD;
    #pragma unroll
    for (int nt = 0; nt < 8; ++nt) {
        int d = nt * 8 + 2 * qc;
        *(float2*)(o0 + d) = make_float2(rnaf(of[nt][0] * inv0),
                                         rnaf(of[nt][1] * inv0));
        *(float2*)(o1 + d) = make_float2(rnaf(of[nt][2] * inv1),
                                         rnaf(of[nt][3] * inv1));
    }
}

// ---------------------------------------------------------------------------
extern "C" void kernel_launch(void* const* d_in, const int* in_sizes, int n_in,
                              void* d_out, int out_size)
{
    const float* x      = (const float*)d_in[0];
    const float* w_qkv  = (const float*)d_in[1];
    const float* w_proj = (const float*)d_in[2];
    const float* b_proj = (const float*)d_in[3];
    float* out = (float*)d_out;

    cudaFuncSetAttribute(gemm_qkv,  cudaFuncAttributeMaxDynamicSharedMemorySize, GSM1);
    cudaFuncSetAttribute(gemm_proj, cudaFuncAttributeMaxDynamicSharedMemorySize, GSM2);
    cudaFuncSetAttribute(attn_mma,  cudaFuncAttributeMaxDynamicSharedMemorySize, ATT_SMEM);

    int n8 = N8X + N8Q + N8P;
    prep_all<<<(n8 + 255) / 256, 256>>>(x, w_qkv, w_proj);

    gemm_qkv<<<dim3(MROWS/128, 3*DIM/128), 256, GSM1>>>();
    attn_mma<<<dim3(SEQ/128, BH), 256, ATT_SMEM>>>();
    gemm_proj<<<dim3(MROWS/128, DIM/128), 256, GSM2>>>(b_proj, out);
}

// round 17
// speedup vs baseline: 1.2993x; 1.1407x over previous
#include <cuda_runtime.h>
#include <cstdint>

#define BATCH 4
#define SEQ   2048
#define DIM   768
#define NH    12
#define HD    64
#define BH    (BATCH*NH)          // 48
#define MROWS (BATCH*SEQ)         // 8192
#define SCALE 0.125f
#define LOG2E 1.4426950408889634f

// Scratch (allocation-free rule: __device__ globals)
__device__ float g_Q[BH*SEQ*HD];         // natural, fp32
__device__ float g_K[BH*SEQ*HD];         // d-permuted 8-groups, tf32
__device__ float g_V[BH*SEQ*HD];         // natural, tf32
__device__ float g_AO[BATCH*SEQ*DIM];    // natural, tf32
__device__ float g_Xr[MROWS*DIM];        // k-permuted, tf32 (GEMM1 A)
__device__ float g_Wqkvr[3*DIM*DIM];     // k-permuted, tf32 (GEMM1 B)
__device__ float g_Wprojr[DIM*DIM];      // natural, tf32   (GEMM2 B)

__device__ __forceinline__ uint32_t smem_u32(const void* p) {
    uint32_t a;
    asm("{ .reg .u64 t; cvta.to.shared.u64 t, %1; cvt.u32.u64 %0, t; }"
        : "=r"(a) : "l"(p));
    return a;
}

__device__ __forceinline__ uint32_t f2tf32(float x) {
    uint32_t r;
    asm("cvt.rna.tf32.f32 %0, %1;" : "=r"(r) : "f"(x));
    return r;
}
__device__ __forceinline__ float rnaf(float x) {
    return __uint_as_float(f2tf32(x));
}

__device__ __forceinline__ float ex2(float x) {
    float r;
    asm("ex2.approx.ftz.f32 %0, %1;" : "=f"(r) : "f"(x));
    return r;
}

__device__ __forceinline__ void cpa16(uint32_t dst, const void* src) {
    asm volatile("cp.async.cg.shared.global [%0], [%1], 16;"
                 :: "r"(dst), "l"(src));
}
#define CP_COMMIT() asm volatile("cp.async.commit_group;" ::: "memory")
#define CP_WAIT1()  asm volatile("cp.async.wait_group 1;" ::: "memory")
#define CP_WAIT0()  asm volatile("cp.async.wait_group 0;" ::: "memory")

__device__ __forceinline__ void mma_tf32(float c[4], uint32_t a0, uint32_t a1,
                                         uint32_t a2, uint32_t a3,
                                         uint32_t b0, uint32_t b1) {
    asm volatile(
        "mma.sync.aligned.m16n8k8.row.col.f32.tf32.tf32.f32 "
        "{%0,%1,%2,%3}, {%4,%5,%6,%7}, {%8,%9}, {%0,%1,%2,%3};"
        : "+f"(c[0]), "+f"(c[1]), "+f"(c[2]), "+f"(c[3])
        : "r"(a0), "r"(a1), "r"(a2), "r"(a3), "r"(b0), "r"(b1));
}

// ---------------------------------------------------------------------------
// Fused prep (one launch): tf32-round everything; k-permute x and w_qkv
// (8-group order 0,4,1,5,2,6,3,7); w_proj natural.
// ---------------------------------------------------------------------------
#define N8X (MROWS*DIM/8)
#define N8Q (3*DIM*DIM/8)
#define N8P (DIM*DIM/8)

__global__ __launch_bounds__(256) void prep_all(
    const float* __restrict__ x, const float* __restrict__ wq,
    const float* __restrict__ wp)
{
    int i = blockIdx.x * 256 + threadIdx.x;
    const float* s; float* d; int idx; bool perm;
    if (i < N8X)            { s = x;  d = g_Xr;    idx = i;             perm = true; }
    else if (i < N8X + N8Q) { s = wq; d = g_Wqkvr; idx = i - N8X;       perm = true; }
    else if (i < N8X + N8Q + N8P) { s = wp; d = g_Wprojr; idx = i - N8X - N8Q; perm = false; }
    else return;

    float4 a = ((const float4*)s)[2*idx];
    float4 b = ((const float4*)s)[2*idx+1];
    float4 o0, o1;
    if (perm) {
        o0.x = rnaf(a.x); o0.y = rnaf(b.x); o0.z = rnaf(a.y); o0.w = rnaf(b.y);
        o1.x = rnaf(a.z); o1.y = rnaf(b.z); o1.z = rnaf(a.w); o1.w = rnaf(b.w);
    } else {
        o0.x = rnaf(a.x); o0.y = rnaf(a.y); o0.z = rnaf(a.z); o0.w = rnaf(a.w);
        o1.x = rnaf(b.x); o1.y = rnaf(b.y); o1.z = rnaf(b.z); o1.w = rnaf(b.w);
    }
    ((float4*)d)[2*idx]   = o0;
    ((float4*)d)[2*idx+1] = o1;
}

// ---------------------------------------------------------------------------
// GEMM1 (validated ~174us): qkv = Xr x Wqkvr. cp.async 2-stage ring, SSTR=40,
// k-permuted LDS.64 fragments. Epilogue: Q raw natural, V rounded natural,
// K rounded + d-PERMUTED (for attention's LDS.64 QK B-fragments).
// ---------------------------------------------------------------------------
#define KT     32
#define SSTR1  40
#define CH1    (128 * SSTR1)
#define GB1    (2 * CH1)
#define GSM1   (2 * GB1 * 4)            // 81920

__global__ __launch_bounds__(256) void gemm_qkv()
{
    extern __shared__ float smf[];
    uint32_t sbase = smem_u32(smf);

    const float* A = g_Xr;
    const float* W = g_Wqkvr;
    int tid  = threadIdx.x;
    int w    = tid >> 5, lane = tid & 31;
    int gr   = lane >> 2, qc = lane & 3;
    int wm   = (w & 1) * 64;
    int wn   = (w >> 1) * 32;
    int bm   = blockIdx.x * 128;
    int bn   = blockIdx.y * 128;

    const float* ag[4]; const float* wg[4]; uint32_t soff[4];
    #pragma unroll
    for (int i = 0; i < 4; ++i) {
        int e   = tid + i * 256;
        int row = e >> 3;
        int ks4 = (e & 7) * 4;
        ag[i]   = A + (size_t)(bm + row) * DIM + ks4;
        wg[i]   = W + (size_t)(bn + row) * DIM + ks4;
        soff[i] = (uint32_t)(row * SSTR1 + ks4) * 4u;
    }

    float acc[4][4][4];
    #pragma unroll
    for (int mt = 0; mt < 4; ++mt)
        #pragma unroll
        for (int nt = 0; nt < 4; ++nt)
            #pragma unroll
            for (int i = 0; i < 4; ++i) acc[mt][nt][i] = 0.f;

    const int NC = DIM / KT;

    #pragma unroll
    for (int i = 0; i < 4; ++i) {
        cpa16(sbase + soff[i], ag[i]);
        cpa16(sbase + CH1 * 4 + soff[i], wg[i]);
    }
    CP_COMMIT();

    int buf = 0;
    for (int c = 0; c < NC; ++c) {
        CP_WAIT0();
        __syncthreads();

        if (c + 1 < NC) {
            uint32_t nbb = sbase + (uint32_t)(buf ^ 1) * GB1 * 4u;
            #pragma unroll
            for (int i = 0; i < 4; ++i) {
                cpa16(nbb + soff[i], ag[i] + (c + 1) * KT);
                cpa16(nbb + CH1 * 4 + soff[i], wg[i] + (c + 1) * KT);
            }
            CP_COMMIT();
        }

        const uint32_t* As = (const uint32_t*)(smf + buf * GB1);
        const uint32_t* Bs = As + CH1;

        #pragma unroll
        for (int ks = 0; ks < KT / 8; ++ks) {
            int k0 = ks * 8;
            uint32_t af[4][4], bf[4][2];
            #pragma unroll
            for (int mt = 0; mt < 4; ++mt) {
                uint2 v0 = *(const uint2*)
                    (As + (wm + mt * 16 + gr) * SSTR1 + k0 + 2 * qc);
                uint2 v1 = *(const uint2*)
                    (As + (wm + mt * 16 + 8 + gr) * SSTR1 + k0 + 2 * qc);
                af[mt][0] = v0.x; af[mt][2] = v0.y;
                af[mt][1] = v1.x; af[mt][3] = v1.y;
            }
            #pragma unroll
            for (int nt = 0; nt < 4; ++nt) {
                uint2 v = *(const uint2*)
                    (Bs + (wn + nt * 8 + gr) * SSTR1 + k0 + 2 * qc);
                bf[nt][0] = v.x; bf[nt][1] = v.y;
            }
            #pragma unroll
            for (int mt = 0; mt < 4; ++mt)
                #pragma unroll
                for (int nt = 0; nt < 4; ++nt)
                    mma_tf32(acc[mt][nt], af[mt][0], af[mt][1], af[mt][2],
                             af[mt][3], bf[nt][0], bf[nt][1]);
        }
        buf ^= 1;
    }

    int scol = bn + wn;
    int s   = scol / DIM;
    int rem = scol % DIM;
    int h   = rem / HD;
    int d0  = rem % HD;
    if (s == 1) {
        // K: tf32-rounded, d-PERMUTED within 8-groups (col 2qc -> p1, 2qc+1 -> p2).
        int p1 = (qc < 2) ? 4 * qc : 4 * qc - 7;
        int p2 = (qc < 2) ? 4 * qc + 2 : 4 * qc - 5;
        #pragma unroll
        for (int mt = 0; mt < 4; ++mt) {
            int r0 = bm + wm + mt * 16 + gr;
            int b  = r0 >> 11, n = r0 & (SEQ - 1);
            float* base = g_K + ((size_t)(b * NH + h) * SEQ + n) * HD;
            #pragma unroll
            for (int nt = 0; nt < 4; ++nt) {
                int dg = d0 + nt * 8;
                base[dg + p1]          = rnaf(acc[mt][nt][0]);
                base[dg + p2]          = rnaf(acc[mt][nt][1]);
                base[8 * HD + dg + p1] = rnaf(acc[mt][nt][2]);
                base[8 * HD + dg + p2] = rnaf(acc[mt][nt][3]);
            }
        }
    } else {
        float* dst = (s == 0) ? g_Q : g_V;
        bool rnd = (s == 2);
        #pragma unroll
        for (int mt = 0; mt < 4; ++mt) {
            int r0 = bm + wm + mt * 16 + gr;
            int b  = r0 >> 11, n = r0 & (SEQ - 1);
            float* base = dst + ((size_t)(b * NH + h) * SEQ + n) * HD;
            #pragma unroll
            for (int nt = 0; nt < 4; ++nt) {
                int d = d0 + nt * 8 + 2 * qc;
                float v0 = acc[mt][nt][0], v1 = acc[mt][nt][1];
                float v2 = acc[mt][nt][2], v3 = acc[mt][nt][3];
                if (rnd) { v0 = rnaf(v0); v1 = rnaf(v1);
                           v2 = rnaf(v2); v3 = rnaf(v3); }
                *(float2*)(base + d) = make_float2(v0, v1);
                *(float2*)(base + 8 * HD + d) = make_float2(v2, v3);
            }
        }
    }
}

// ---------------------------------------------------------------------------
// GEMM2 (R8-validated): out = AO x Wprojr + bias. 3-stage cp.async ring,
// SSTR=36, scalar fragment loads, natural layouts.
// ---------------------------------------------------------------------------
#define SSTR2  36
#define CH2    (128 * SSTR2)
#define GB2    (2 * CH2)
#define GSM2   (3 * GB2 * 4)            // 110592

__global__ __launch_bounds__(256) void gemm_proj(
    const float* __restrict__ bias, float* __restrict__ out)
{
    extern __shared__ float smf[];
    uint32_t sbase = smem_u32(smf);

    const float* A = g_AO;
    const float* W = g_Wprojr;
    int tid  = threadIdx.x;
    int w    = tid >> 5, lane = tid & 31;
    int gr   = lane >> 2, qc = lane & 3;
    int wm   = (w & 1) * 64;
    int wn   = (w >> 1) * 32;
    int bm   = blockIdx.x * 128;
    int bn   = blockIdx.y * 128;

    const float* ag[4]; const float* wg[4]; uint32_t soff[4];
    #pragma unroll
    for (int i = 0; i < 4; ++i) {
        int e   = tid + i * 256;
        int row = e >> 3;
        int ks4 = (e & 7) * 4;
        ag[i]   = A + (size_t)(bm + row) * DIM + ks4;
        wg[i]   = W + (size_t)(bn + row) * DIM + ks4;
        soff[i] = (uint32_t)(row * SSTR2 + ks4) * 4u;
    }

    float acc[4][4][4];
    #pragma unroll
    for (int mt = 0; mt < 4; ++mt)
        #pragma unroll
        for (int nt = 0; nt < 4; ++nt)
            #pragma unroll
            for (int i = 0; i < 4; ++i) acc[mt][nt][i] = 0.f;

    const int NC = DIM / KT;

    #pragma unroll
    for (int i = 0; i < 4; ++i) {
        cpa16(sbase + soff[i], ag[i]);
        cpa16(sbase + CH2 * 4 + soff[i], wg[i]);
    }
    CP_COMMIT();
    #pragma unroll
    for (int i = 0; i < 4; ++i) {
        cpa16(sbase + GB2 * 4 + soff[i], ag[i] + KT);
        cpa16(sbase + (GB2 + CH2) * 4 + soff[i], wg[i] + KT);
    }
    CP_COMMIT();

    int buf = 0;
    for (int c = 0; c < NC; ++c) {
        if (c + 1 < NC) CP_WAIT1(); else CP_WAIT0();
        __syncthreads();

        if (c + 2 < NC) {
            int nb = buf + 2; if (nb >= 3) nb -= 3;
            uint32_t nbb = sbase + (uint32_t)nb * GB2 * 4u;
            #pragma unroll
            for (int i = 0; i < 4; ++i) {
                cpa16(nbb + soff[i], ag[i] + (c + 2) * KT);
                cpa16(nbb + CH2 * 4 + soff[i], wg[i] + (c + 2) * KT);
            }
            CP_COMMIT();
        }

        const uint32_t* As = (const uint32_t*)(smf + buf * GB2);
        const uint32_t* Bs = As + CH2;

        #pragma unroll
        for (int ks = 0; ks < KT / 8; ++ks) {
            int k0 = ks * 8;
            uint32_t af[4][4], bf[4][2];
            #pragma unroll
            for (int mt = 0; mt < 4; ++mt) {
                const uint32_t* p = As + (wm + mt * 16 + gr) * SSTR2 + k0 + qc;
                af[mt][0] = p[0];
                af[mt][1] = p[8 * SSTR2];
                af[mt][2] = p[4];
                af[mt][3] = p[8 * SSTR2 + 4];
            }
            #pragma unroll
            for (int nt = 0; nt < 4; ++nt) {
                const uint32_t* p = Bs + (wn + nt * 8 + gr) * SSTR2 + k0 + qc;
                bf[nt][0] = p[0];
                bf[nt][1] = p[4];
            }
            #pragma unroll
            for (int mt = 0; mt < 4; ++mt)
                #pragma unroll
                for (int nt = 0; nt < 4; ++nt)
                    mma_tf32(acc[mt][nt], af[mt][0], af[mt][1], af[mt][2],
                             af[mt][3], bf[nt][0], bf[nt][1]);
        }
        if (++buf >= 3) buf -= 3;
    }

    int scol = bn + wn;
    #pragma unroll
    for (int mt = 0; mt < 4; ++mt) {
        int r0 = bm + wm + mt * 16 + gr;
        float* base = out + (size_t)r0 * DIM;
        #pragma unroll
        for (int nt = 0; nt < 4; ++nt) {
            int cb = scol + nt * 8 + 2 * qc;
            float2 bv = *(const float2*)(bias + cb);
            *(float2*)(base + cb) =
                make_float2(acc[mt][nt][0] + bv.x, acc[mt][nt][1] + bv.y);
            *(float2*)(base + 8 * DIM + cb) =
                make_float2(acc[mt][nt][2] + bv.x, acc[mt][nt][3] + bv.y);
        }
    }
}

// ---------------------------------------------------------------------------
// Flash attention: R8 pipeline + per-region strides, all audited conflict-free:
//   K (d-permuted) & V at stride 72: QK LDS.64 frags + PV scalar gather
//   P at stride 68: A-fragment scalar loads
// Softmax arithmetic byte-identical to R8/R16 (rel_err checksum 6.35633e-4).
// ---------------------------------------------------------------------------
#define ABC   64
#define KVSTR 72
#define PSTR  68
#define KBUF_WORDS (64 * KVSTR)                   // 4608
#define V_OFF   (2 * KBUF_WORDS)
#define P_OFF   (4 * KBUF_WORDS)
#define ATT_SMEM ((4 * KBUF_WORDS + 128 * PSTR) * 4)   // 108544 bytes

__global__ __launch_bounds__(256) void attn_mma()
{
    extern __shared__ float sh[];
    uint32_t sbase = smem_u32(sh);
    float* Ps = sh + P_OFF;

    int bh  = blockIdx.y;
    int q0  = blockIdx.x * 128;
    int tid = threadIdx.x;
    int w   = tid >> 5, lane = tid & 31;
    int gr  = lane >> 2, qc = lane & 3;
    int wm  = w * 16;

    const float* Qb = g_Q + ((size_t)bh * SEQ + q0) * HD;
    const float* Kb = g_K + (size_t)bh * SEQ * HD;
    const float* Vb = g_V + (size_t)bh * SEQ * HD;

    const float qs = SCALE * LOG2E;
    int r0 = wm + gr;
    uint32_t qf[8][4];
    #pragma unroll
    for (int kt = 0; kt < 8; ++kt) {
        int c = kt * 8 + qc;
        qf[kt][0] = f2tf32(Qb[(size_t)r0 * HD + c] * qs);
        qf[kt][1] = f2tf32(Qb[(size_t)(r0 + 8) * HD + c] * qs);
        qf[kt][2] = f2tf32(Qb[(size_t)r0 * HD + c + 4] * qs);
        qf[kt][3] = f2tf32(Qb[(size_t)(r0 + 8) * HD + c + 4] * qs);
    }

    const float* kg[4]; const float* vg[4]; uint32_t soff[4];
    #pragma unroll
    for (int i = 0; i < 4; ++i) {
        int slot = tid + i * 256;
        int key  = slot >> 4;
        int d4   = (slot & 15) * 4;
        kg[i]   = Kb + key * HD + d4;
        vg[i]   = Vb + key * HD + d4;
        soff[i] = (uint32_t)(key * KVSTR + d4) * 4u;
    }

    float of[8][4];
    #pragma unroll
    for (int nt = 0; nt < 8; ++nt)
        #pragma unroll
        for (int i = 0; i < 4; ++i) of[nt][i] = 0.f;
    float m0 = -1e30f, m1 = -1e30f, l0 = 0.f, l1 = 0.f;

    const int NT = SEQ / ABC;   // 32

    #pragma unroll
    for (int i = 0; i < 4; ++i) {
        cpa16(sbase + soff[i], kg[i]);
        cpa16(sbase + V_OFF * 4 + soff[i], vg[i]);
    }
    CP_COMMIT();

    #pragma unroll 1
    for (int t = 0; t < NT; ++t) {
        if (t + 1 < NT) {
            uint32_t kb = sbase + (uint32_t)((t + 1) & 1) * KBUF_WORDS * 4u;
            size_t goff = (size_t)(t + 1) * ABC * HD;
            #pragma unroll
            for (int i = 0; i < 4; ++i) {
                cpa16(kb + soff[i], kg[i] + goff);
                cpa16(kb + V_OFF * 4 + soff[i], vg[i] + goff);
            }
            CP_COMMIT();
            CP_WAIT1();
        } else {
            CP_WAIT0();
        }
        __syncthreads();   // tile t visible

        const float* Kt = sh + (t & 1) * KBUF_WORDS;
        const float* Vt = Kt + V_OFF;

        // S = Q K^T  (K d-permuted: LDS.64 fragment pairs, conflict-free)
        float sf[8][4];
        #pragma unroll
        for (int nt = 0; nt < 8; ++nt)
            #pragma unroll
            for (int i = 0; i < 4; ++i) sf[nt][i] = 0.f;
        #pragma unroll
        for (int kt = 0; kt < 8; ++kt) {
            int k0 = kt * 8;
            #pragma unroll
            for (int nt = 0; nt < 8; ++nt) {
                uint2 v = *(const uint2*)
                    (Kt + (nt * 8 + gr) * KVSTR + k0 + 2 * qc);
                mma_tf32(sf[nt], qf[kt][0], qf[kt][1], qf[kt][2], qf[kt][3],
                         v.x, v.y);
            }
        }

        // Online softmax (log2 domain, hardware ex2) — R8 arithmetic exactly
        float tm0 = -1e30f, tm1 = -1e30f;
        #pragma unroll
        for (int nt = 0; nt < 8; ++nt) {
            tm0 = fmaxf(tm0, fmaxf(sf[nt][0], sf[nt][1]));
            tm1 = fmaxf(tm1, fmaxf(sf[nt][2], sf[nt][3]));
        }
        tm0 = fmaxf(tm0, __shfl_xor_sync(0xffffffffu, tm0, 1));
        tm0 = fmaxf(tm0, __shfl_xor_sync(0xffffffffu, tm0, 2));
        tm1 = fmaxf(tm1, __shfl_xor_sync(0xffffffffu, tm1, 1));
        tm1 = fmaxf(tm1, __shfl_xor_sync(0xffffffffu, tm1, 2));

        float nm0 = fmaxf(m0, tm0), nm1 = fmaxf(m1, tm1);
        float c0 = ex2(m0 - nm0), c1 = ex2(m1 - nm1);
        m0 = nm0; m1 = nm1;

        float rs0 = 0.f, rs1 = 0.f;
        float* prow0 = Ps + (wm + gr) * PSTR + 2 * qc;
        float* prow1 = prow0 + 8 * PSTR;
        #pragma unroll
        for (int nt = 0; nt < 8; ++nt) {
            float p0 = rnaf(ex2(sf[nt][0] - nm0));
            float p1 = rnaf(ex2(sf[nt][1] - nm0));
            float p2 = rnaf(ex2(sf[nt][2] - nm1));
            float p3 = rnaf(ex2(sf[nt][3] - nm1));
            rs0 += p0 + p1;
            rs1 += p2 + p3;
            *(float2*)(prow0 + nt * 8) = make_float2(p0, p1);
            *(float2*)(prow1 + nt * 8) = make_float2(p2, p3);
        }
        rs0 += __shfl_xor_sync(0xffffffffu, rs0, 1);
        rs0 += __shfl_xor_sync(0xffffffffu, rs0, 2);
        rs1 += __shfl_xor_sync(0xffffffffu, rs1, 1);
        rs1 += __shfl_xor_sync(0xffffffffu, rs1, 2);
        l0 = l0 * c0 + rs0;
        l1 = l1 * c1 + rs1;

        #pragma unroll
        for (int nt = 0; nt < 8; ++nt) {
            of[nt][0] *= c0; of[nt][1] *= c0;
            of[nt][2] *= c1; of[nt][3] *= c1;
        }
        __syncwarp();   // P is warp-private

        // O += P V  (P stride 68: conflict-free A-frags;
        //            V stride 72: conflict-free scalar column gather)
        #pragma unroll
        for (int kt = 0; kt < 8; ++kt) {
            int k0 = kt * 8;
            const uint32_t* ap =
                (const uint32_t*)(Ps + (wm + gr) * PSTR + k0 + qc);
            uint32_t a0 = ap[0];
            uint32_t a1 = ap[8 * PSTR];
            uint32_t a2 = ap[4];
            uint32_t a3 = ap[8 * PSTR + 4];
            #pragma unroll
            for (int nt = 0; nt < 8; ++nt) {
                const uint32_t* vp =
                    (const uint32_t*)(Vt + (k0 + qc) * KVSTR + nt * 8 + gr);
                mma_tf32(of[nt], a0, a1, a2, a3, vp[0], vp[4 * KVSTR]);
            }
        }
        __syncthreads();   // buffer reads done
    }

    // Epilogue: write AO tf32-rounded, natural float2 layout.
    float inv0 = 1.f / l0, inv1 = 1.f / l1;
    int b = bh / NH, h = bh % NH;
    int n0 = q0 + wm + gr;
    float* o0 = g_AO + ((size_t)(b * SEQ + n0)) * DIM + h * HD;
    float* o1 = g_AO + ((size_t)(b * SEQ + n0 + 8)) * DIM + h * HD;
    #pragma unroll
    for (int nt = 0; nt < 8; ++nt) {
        int d = nt * 8 + 2 * qc;
        *(float2*)(o0 + d) = make_float2(rnaf(of[nt][0] * inv0),
                                         rnaf(of[nt][1] * inv0));
        *(float2*)(o1 + d) = make_float2(rnaf(of[nt][2] * inv1),
                                         rnaf(of[nt][3] * inv1));
    }
}

// ---------------------------------------------------------------------------
extern "C" void kernel_launch(void* const* d_in, const int* in_sizes, int n_in,
                              void* d_out, int out_size)
{
    const float* x      = (const float*)d_in[0];
    const float* w_qkv  = (const float*)d_in[1];
    const float* w_proj = (const float*)d_in[2];
    const float* b_proj = (const float*)d_in[3];
    float* out = (float*)d_out;

    cudaFuncSetAttribute(gemm_qkv,  cudaFuncAttributeMaxDynamicSharedMemorySize, GSM1);
    cudaFuncSetAttribute(gemm_proj, cudaFuncAttributeMaxDynamicSharedMemorySize, GSM2);
    cudaFuncSetAttribute(attn_mma,  cudaFuncAttributeMaxDynamicSharedMemorySize, ATT_SMEM);

    int n8 = N8X + N8Q + N8P;
    prep_all<<<(n8 + 255) / 256, 256>>>(x, w_qkv, w_proj);

    gemm_qkv<<<dim3(MROWS/128, 3*DIM/128), 256, GSM1>>>();
    attn_mma<<<dim3(SEQ/128, BH), 256, ATT_SMEM>>>();
    gemm_proj<<<dim3(MROWS/128, DIM/128), 256, GSM2>>>(b_proj, out);
}